// round 7
// baseline (speedup 1.0000x reference)
#include <cuda_runtime.h>
#include <cstdint>

// FinePreprocess: gather 5x5 windows (stride 4, pad 2) from two NCHW f32
// feature maps at per-match window indices. Output is the concatenation of
// (M,25,C) for feat0 then feat1; within a match the flat layout is
// c*25 + wy*5 + wx (flat reinterpretation of the reference's
// transpose(0,3,1,2).reshape(M,C*25).reshape(M,25,C) chain).

#define FP_N 4
#define FP_C 128
#define FP_H 240
#define FP_W 320
#define FP_WK 5
#define FP_STRIDE 4
#define FP_PAD 2
#define FP_OUTW 80   // (W + 2*PAD - WK)/STRIDE + 1
#define FP_OUTH 60
#define FP_L (FP_OUTW * FP_OUTH)   // 4800

// One thread per (feature, m, c, wy): 5 loads, 5 stores.
__global__ void __launch_bounds__(256)
fine_gather_kernel(const float* __restrict__ feat0,
                   const float* __restrict__ feat1,
                   const int* __restrict__ b_ids,
                   const int* __restrict__ i_ids,
                   const int* __restrict__ j_ids,
                   float* __restrict__ out,
                   int M)
{
    int t = blockIdx.x * blockDim.x + threadIdx.x;
    int total = 2 * M * FP_C * FP_WK;
    if (t >= total) return;

    int wy = t % FP_WK;
    int r1 = t / FP_WK;
    int c  = r1 % FP_C;
    int r2 = r1 / FP_C;
    int m  = r2 % M;
    int f  = r2 / M;            // 0 -> feat0/i_ids, 1 -> feat1/j_ids

    // ids are warp-near-uniform (640 threads share one m) -> L1 broadcast.
    // Clamp defensively: no-op for valid data, turns any residual dtype
    // mismatch into a rel_err signal instead of an illegal access.
    int b   = min(max(b_ids[m], 0), FP_N - 1);
    int idx = min(max(f ? j_ids[m] : i_ids[m], 0), FP_L - 1);

    int gy = idx / FP_OUTW;
    int gx = idx - gy * FP_OUTW;
    int h  = gy * FP_STRIDE + wy - FP_PAD;
    int w0 = gx * FP_STRIDE - FP_PAD;

    // output: block per (f, m) of C*25 floats, inner layout c*25 + wy*5 + wx
    int oidx = ((f * M + m) * FP_C + c) * (FP_WK * FP_WK) + wy * FP_WK;
    float* __restrict__ o = out + oidx;

    float v0 = 0.f, v1 = 0.f, v2 = 0.f, v3 = 0.f, v4 = 0.f;
    if (h >= 0 && h < FP_H) {
        const float* __restrict__ src = f ? feat1 : feat0;
        const float* __restrict__ row =
            src + (((long long)b * FP_C + c) * FP_H + h) * FP_W;
        int w;
        w = w0 + 0; if (w >= 0 && w < FP_W) v0 = __ldg(row + w);
        w = w0 + 1; if (w >= 0 && w < FP_W) v1 = __ldg(row + w);
        w = w0 + 2; if (w >= 0 && w < FP_W) v2 = __ldg(row + w);
        w = w0 + 3; if (w >= 0 && w < FP_W) v3 = __ldg(row + w);
        w = w0 + 4; if (w >= 0 && w < FP_W) v4 = __ldg(row + w);
    }
    o[0] = v0; o[1] = v1; o[2] = v2; o[3] = v3; o[4] = v4;
}

extern "C" void kernel_launch(void* const* d_in, const int* in_sizes, int n_in,
                              void* d_out, int out_size)
{
    // metadata order: feat_f0, feat_f1, hw0_f, hw0_c, b_ids, i_ids, j_ids
    const float* feat0 = (const float*)d_in[0];
    const float* feat1 = (const float*)d_in[1];
    const int*   b_ids = (const int*)d_in[4];
    const int*   i_ids = (const int*)d_in[5];
    const int*   j_ids = (const int*)d_in[6];
    float* out = (float*)d_out;

    int M = in_sizes[4];   // 6000

    int total   = 2 * M * FP_C * FP_WK;
    int threads = 256;
    int blocks  = (total + threads - 1) / threads;

    fine_gather_kernel<<<blocks, threads>>>(feat0, feat1, b_ids, i_ids, j_ids, out, M);
}

// round 8
// speedup vs baseline: 1.1327x; 1.1327x over previous
#include <cuda_runtime.h>
#include <cstdint>

// FinePreprocess: gather 5x5 windows (stride 4, pad 2) from two NCHW f32
// feature maps at per-match window indices. Output = concat[(M,25,C) f0,
// (M,25,C) f1]; per-match flat layout is c*25 + wy*5 + wx.
//
// R8 design: one block per (feature, match) patch.
//  Phase 1: 640 threads, one (c,wy) row-segment each. w0 = 4*gx-2 is ≡2 mod 4,
//           so the 5-float window is exactly two aligned float4 blocks
//           (elements 4(gx-1) and 4gx) with fixed extraction {A.z,A.w,B.x,B.y,B.z}.
//           Each lane: 2 LDG.128 (1 line each) -> 5 scalar STS into smem laid
//           out in output order (word 5*tid).
//  Phase 2: copy 800 float4 out fully coalesced (full-sector STG.128).

#define FP_N 4
#define FP_C 128
#define FP_H 240
#define FP_W 320
#define FP_OUTW 80
#define FP_L 4800           // 60*80
#define PATCH_WORDS 3200    // C*25
#define PATCH_VEC4 800

__global__ void __launch_bounds__(640, 3)
fine_gather_kernel(const float* __restrict__ feat0,
                   const float* __restrict__ feat1,
                   const int* __restrict__ b_ids,
                   const int* __restrict__ i_ids,
                   const int* __restrict__ j_ids,
                   float* __restrict__ out,
                   int M)
{
    __shared__ float s[PATCH_WORDS];

    int blk = blockIdx.x;            // [0, 2M): feat0 patches then feat1 patches
    int f   = blk >= M;
    int m   = f ? blk - M : blk;
    int tid = threadIdx.x;           // 0..639 == c*5 + wy

    // block-uniform scalars (L1 broadcast). Clamp = no-op on valid data.
    int b   = min(max(b_ids[m], 0), FP_N - 1);
    int idx = min(max((f ? j_ids : i_ids)[m], 0), FP_L - 1);
    int gy  = idx / FP_OUTW;
    int gx  = idx - gy * FP_OUTW;

    int c  = tid / 5;
    int wy = tid - 5 * c;
    int h  = gy * 4 + wy - 2;

    const float* __restrict__ src = f ? feat1 : feat0;

    float4 A = make_float4(0.f, 0.f, 0.f, 0.f);
    float4 B = make_float4(0.f, 0.f, 0.f, 0.f);
    if (h >= 0 && h < FP_H) {
        const float4* __restrict__ row4 = (const float4*)
            (src + (((long long)b * FP_C + c) * FP_H + h) * FP_W);
        if (gx > 0)                      // block-uniform branch
            A = __ldg(row4 + (gx - 1));  // elements 4gx-4 .. 4gx-1
        B = __ldg(row4 + gx);            // elements 4gx   .. 4gx+3
    }
    // window = elements 4gx-2 .. 4gx+2  ->  {A.z, A.w, B.x, B.y, B.z}
    float* __restrict__ srow = s + tid * 5;   // word 5*(c*5+wy) = c*25+wy*5
    srow[0] = A.z;
    srow[1] = A.w;
    srow[2] = B.x;
    srow[3] = B.y;
    srow[4] = B.z;

    __syncthreads();

    // Phase 2: coalesced full-sector writeout, 800 float4 per patch.
    float4* __restrict__ out4 = (float4*)out + (long long)blk * PATCH_VEC4;
    const float4* __restrict__ s4 = (const float4*)s;
    out4[tid] = s4[tid];
    if (tid < PATCH_VEC4 - 640)
        out4[640 + tid] = s4[640 + tid];
}

extern "C" void kernel_launch(void* const* d_in, const int* in_sizes, int n_in,
                              void* d_out, int out_size)
{
    // metadata order: feat_f0, feat_f1, hw0_f, hw0_c, b_ids, i_ids, j_ids
    const float* feat0 = (const float*)d_in[0];
    const float* feat1 = (const float*)d_in[1];
    const int*   b_ids = (const int*)d_in[4];
    const int*   i_ids = (const int*)d_in[5];
    const int*   j_ids = (const int*)d_in[6];
    float* out = (float*)d_out;

    int M = in_sizes[4];   // 6000

    fine_gather_kernel<<<2 * M, 640>>>(feat0, feat1, b_ids, i_ids, j_ids, out, M);
}